// round 11
// baseline (speedup 1.0000x reference)
#include <cuda_runtime.h>
#include <cuda_bf16.h>
#include <math.h>

#define N_NODE 100000
#define NE     150000
#define DK     512
#define NH     8
#define CAP    64

// ---------------- scratch (device globals, allocation-free) ----------------
__device__ __nv_bfloat16 g_h_o[(size_t)N_NODE * DK];
__device__ __nv_bfloat16 g_h_e[(size_t)N_NODE * DK];
__device__ __nv_bfloat16 g_out0[(size_t)N_NODE * DK];
__device__ __nv_bfloat16 g_out1[(size_t)N_NODE * DK];

__device__ __nv_bfloat16 g_bw_o[DK * DK];   // bf16 weights, [k, n] layout
__device__ __nv_bfloat16 g_bw_e[DK * DK];
__device__ __nv_bfloat16 g_bw_k[DK * DK];

__device__ float g_a_e_src[(size_t)N_NODE * NH];
__device__ float g_a_o_dst_e2o[(size_t)N_NODE * NH];
__device__ float g_a_o_src_o2o[(size_t)N_NODE * NH];
__device__ float g_a_o_dst_o2o[(size_t)N_NODE * NH];

__device__ int g_deg0[N_NODE];
__device__ int g_deg1[N_NODE];
__device__ int g_slots0[(size_t)N_NODE * CAP];
__device__ int g_slots1[(size_t)N_NODE * CAP];

__device__ float g_kdot[2];
__device__ float g_outsum[2 * DK];

__device__ __forceinline__ unsigned pack_bf16(float x, float y) {
    __nv_bfloat162 h = __floats2bfloat162_rn(x, y);
    return *reinterpret_cast<unsigned*>(&h);
}
__device__ __forceinline__ float2 unpack_bf16(unsigned u) {
    __nv_bfloat162 h = *reinterpret_cast<__nv_bfloat162*>(&u);
    return __bfloat1622float2(h);
}

// ---------------- prep: init counters + all 3 weight converts, one launch ----------------
__global__ void prep_kernel(const float* __restrict__ w0, const float* __restrict__ w1,
                            const float* __restrict__ w2) {
    int i = blockIdx.x * blockDim.x + threadIdx.x;
    const int WP = DK * DK / 2;
    if (i < 3 * WP) {
        const float* W = (i < WP) ? w0 : (i < 2 * WP) ? w1 : w2;
        __nv_bfloat16* O = (i < WP) ? g_bw_o : (i < 2 * WP) ? g_bw_e : g_bw_k;
        int j = (i < WP) ? i : (i < 2 * WP) ? i - WP : i - 2 * WP;
        float2 f = reinterpret_cast<const float2*>(W)[j];
        reinterpret_cast<unsigned*>(O)[j] = pack_bf16(f.x, f.y);
    }
    if (i < N_NODE) { g_deg0[i] = 0; g_deg1[i] = 0; }
    if (i < 2 * DK) g_outsum[i] = 0.f;
    if (i < 2) g_kdot[i] = 0.f;
}

// =====================================================================
// Projection GEMM: C[M,512] = bf16(A_fp32[M,512]) @ B[512,512]
// A: fp32 cp.async into 2-stage LINEAR smem; smem-convert to double-buffered
//    swizzled bf16 buffers (hidden under MMA). B: bf16, 3-stage cp.async.
// Pipeline per chunk ch: [wait 0][sync][issue ch+2][convert ch+1][MMA ch]
// Epilogue: bias + store bf16 C + NATT fused per-head attention dots.
// =====================================================================
#define P_SM_A32  0                     // 2 x 32KB fp32 A stages (linear)
#define P_SM_A16  65536                 // 2 x 16KB bf16 A buffers (swizzled)
#define P_SM_B    98304                 // 3 x 16KB B stages (swizzled)
#define P_SM_BIAS 147456
#define P_SM_AUX  149504
#define P_SM_TOTAL (149504 + 6144)      // 155648

template<int NATT>
__global__ __launch_bounds__(256)
void proj_gemm(const float* __restrict__ A, const __nv_bfloat16* __restrict__ B,
               const float* __restrict__ bias, __nv_bfloat16* __restrict__ Cout,
               const float* __restrict__ av0, const float* __restrict__ av1,
               const float* __restrict__ av2,
               float* __restrict__ aout0, float* __restrict__ aout1,
               float* __restrict__ aout2, int M) {
    extern __shared__ __align__(16) unsigned char dsm[];
    unsigned sbase = (unsigned)__cvta_generic_to_shared(dsm);
    float* bias_sh = (float*)(dsm + P_SM_BIAS);
    float* aux_sh  = (float*)(dsm + P_SM_AUX);

    int tid = threadIdx.x;
    int lane = tid & 31, wid = tid >> 5;
    int warp_m = wid & 3, warp_n = wid >> 2;
    int rowBase = blockIdx.y * 128;
    int colBase = blockIdx.x * 128;

    for (int i = tid; i < DK; i += 256) bias_sh[i] = bias[i];
    for (int i = tid; i < NATT * DK; i += 256) {
        const float* src = (i < DK) ? av0 : (i < 2 * DK) ? av1 : av2;
        aux_sh[i] = src[i & (DK - 1)];
    }

    float c[2][8][4];
#pragma unroll
    for (int i = 0; i < 2; i++)
#pragma unroll
        for (int j = 0; j < 8; j++)
#pragma unroll
            for (int q = 0; q < 4; q++) c[i][j][q] = 0.f;

    // cp.async chunk ch: A fp32 (32KB, linear) + B bf16 (16KB, swizzled)
    auto issue = [&](int ch) {
        unsigned a32 = sbase + P_SM_A32 + (ch & 1) * 32768;
        unsigned bb  = sbase + P_SM_B + (ch % 3) * 16384;
        int k0 = ch * 64;
#pragma unroll
        for (int i = 0; i < 8; i++) {       // A: 2048 x 16B (4 floats)
            int idx = tid + 256 * i;
            int r = idx >> 4, c4 = idx & 15;
            int gr = rowBase + r;
            int sz = (gr < M) ? 16 : 0;
            int ga = (gr < M) ? gr : (M - 1);
            const float* src = A + (size_t)ga * DK + k0 + c4 * 4;
            unsigned dst = a32 + r * 256 + c4 * 16;
            asm volatile("cp.async.cg.shared.global [%0], [%1], 16, %2;"
                         :: "r"(dst), "l"(src), "r"(sz));
        }
#pragma unroll
        for (int i = 0; i < 4; i++) {       // B: 1024 x 16B
            int idx = tid + 256 * i;
            int r = idx >> 4, cch = idx & 15;
            const __nv_bfloat16* src = B + (size_t)(k0 + r) * DK + colBase + cch * 8;
            unsigned dst = bb + (r * 16 + ((cch & 8) | ((cch & 7) ^ (r & 7)))) * 16;
            asm volatile("cp.async.cg.shared.global [%0], [%1], 16;"
                         :: "r"(dst), "l"(src));
        }
    };
    // smem fp32 -> swizzled bf16 (1024 uint4 outputs, 4 per thread)
    auto convert = [&](int ch) {
        const float* a32 = (const float*)(dsm + P_SM_A32 + (ch & 1) * 32768);
        unsigned char* a16 = dsm + P_SM_A16 + (ch & 1) * 16384;
#pragma unroll
        for (int i = 0; i < 4; i++) {
            int o = tid + 256 * i;
            int r = o >> 3, c16 = o & 7;
            const float4* fp = reinterpret_cast<const float4*>(a32 + r * 64 + c16 * 8);
            float4 f0 = fp[0], f1 = fp[1];
            uint4 u = make_uint4(pack_bf16(f0.x, f0.y), pack_bf16(f0.z, f0.w),
                                 pack_bf16(f1.x, f1.y), pack_bf16(f1.z, f1.w));
            unsigned bo = r * 128 + c16 * 16;
            unsigned sw = bo ^ ((bo >> 3) & 0x70);
            *reinterpret_cast<uint4*>(a16 + sw) = u;
        }
    };

    issue(0); asm volatile("cp.async.commit_group;" ::: "memory");
    issue(1); asm volatile("cp.async.commit_group;" ::: "memory");
    asm volatile("cp.async.wait_group 1;" ::: "memory");   // chunk 0 arrived
    __syncthreads();
    convert(0);

    for (int ch = 0; ch < 8; ch++) {
        if (ch + 1 < 8) asm volatile("cp.async.wait_group 0;" ::: "memory"); // chunk ch+1
        __syncthreads();                    // publishes convert(ch) and chunk ch+1
        if (ch + 2 < 8) {
            issue(ch + 2);
            asm volatile("cp.async.commit_group;" ::: "memory");
        }
        if (ch + 1 < 8) convert(ch + 1);    // overlaps with MMA below via warp interleave

        unsigned AsB = sbase + P_SM_A16 + (ch & 1) * 16384;
        unsigned BsB = sbase + P_SM_B + (ch % 3) * 16384;
#pragma unroll
        for (int kk = 0; kk < 4; kk++) {
            unsigned a[2][4], b[8][2];
#pragma unroll
            for (int i = 0; i < 2; i++) {
                int m = lane >> 3;
                int r = warp_m * 32 + i * 16 + (m & 1) * 8 + (lane & 7);
                int cch = kk * 2 + (m >> 1);
                unsigned addr = AsB + r * 128 + ((cch ^ (r & 7)) * 16);
                asm volatile("ldmatrix.sync.aligned.m8n8.x4.shared.b16 {%0,%1,%2,%3}, [%4];"
                             : "=r"(a[i][0]), "=r"(a[i][1]), "=r"(a[i][2]), "=r"(a[i][3]) : "r"(addr));
            }
#pragma unroll
            for (int jp = 0; jp < 4; jp++) {
                int m = lane >> 3;
                int kr = kk * 16 + (m & 1) * 8 + (lane & 7);
                int cch = warp_n * 8 + jp * 2 + (m >> 1);
                unsigned addr = BsB + kr * 256 + (((cch & 8) | ((cch & 7) ^ (kr & 7))) * 16);
                asm volatile("ldmatrix.sync.aligned.m8n8.x4.trans.shared.b16 {%0,%1,%2,%3}, [%4];"
                             : "=r"(b[jp*2][0]), "=r"(b[jp*2][1]), "=r"(b[jp*2+1][0]), "=r"(b[jp*2+1][1])
                             : "r"(addr));
            }
#pragma unroll
            for (int i = 0; i < 2; i++)
#pragma unroll
                for (int j = 0; j < 8; j++) {
                    asm volatile(
                        "mma.sync.aligned.m16n8k16.row.col.f32.bf16.bf16.f32 "
                        "{%0,%1,%2,%3}, {%4,%5,%6,%7}, {%8,%9}, {%0,%1,%2,%3};"
                        : "+f"(c[i][j][0]), "+f"(c[i][j][1]), "+f"(c[i][j][2]), "+f"(c[i][j][3])
                        : "r"(a[i][0]), "r"(a[i][1]), "r"(a[i][2]), "r"(a[i][3]),
                          "r"(b[j][0]), "r"(b[j][1]));
                }
        }
    }

    // ---------------- epilogue: bias + store + fused attention dots ----------------
    int g = lane >> 2, t = lane & 3;
    float aacc[NATT][4];
#pragma unroll
    for (int v = 0; v < NATT; v++)
#pragma unroll
        for (int f = 0; f < 4; f++) aacc[v][f] = 0.f;

#pragma unroll
    for (int j = 0; j < 8; j++) {
        int col = colBase + warp_n * 64 + j * 8 + 2 * t;
        float b0 = bias_sh[col], b1 = bias_sh[col + 1];
#pragma unroll
        for (int i = 0; i < 2; i++) {
            int r0 = rowBase + warp_m * 32 + i * 16 + g;
            float v0 = c[i][j][0] + b0, v1 = c[i][j][1] + b1;
            float v2 = c[i][j][2] + b0, v3 = c[i][j][3] + b1;
            if (r0 < M)
                *reinterpret_cast<unsigned*>(Cout + (size_t)r0 * DK + col) = pack_bf16(v0, v1);
            if (r0 + 8 < M)
                *reinterpret_cast<unsigned*>(Cout + (size_t)(r0 + 8) * DK + col) = pack_bf16(v2, v3);
#pragma unroll
            for (int v = 0; v < NATT; v++) {
                float a0 = aux_sh[v * DK + col], a1 = aux_sh[v * DK + col + 1];
                aacc[v][i * 2 + 0] += v0 * a0 + v1 * a1;
                aacc[v][i * 2 + 1] += v2 * a0 + v3 * a1;
            }
        }
    }
#pragma unroll
    for (int v = 0; v < NATT; v++)
#pragma unroll
        for (int f = 0; f < 4; f++) {
            aacc[v][f] += __shfl_xor_sync(0xffffffffu, aacc[v][f], 1);
            aacc[v][f] += __shfl_xor_sync(0xffffffffu, aacc[v][f], 2);
        }
    if (t == 0) {
        int ghead = blockIdx.x * 2 + warp_n;
#pragma unroll
        for (int f = 0; f < 4; f++) {
            int row = rowBase + warp_m * 32 + (f & 1) * 8 + (f >> 1) * 16 + g;
            if (row < M) {
#pragma unroll
                for (int v = 0; v < NATT; v++) {
                    float* ao = (v == 0) ? aout0 : (v == 1) ? aout1 : aout2;
                    ao[(size_t)row * NH + ghead] = aacc[v][f];
                }
            }
        }
    }
}

// =====================================================================
// k-GEMM: sum_n sum_f tanh((A @ B + bias))*q  -> kdot[z]  (A bf16)
// =====================================================================
#define K_SM_BIAS   98304
#define K_SM_AUX    (98304 + 2048)
#define K_SM_TOTAL  (98304 + 2048 + 2048)

__global__ __launch_bounds__(256)
void ksum_gemm(const __nv_bfloat16* __restrict__ A0, const __nv_bfloat16* __restrict__ A1,
               const __nv_bfloat16* __restrict__ B,
               const float* __restrict__ bias,
               const float* __restrict__ qsem, float* __restrict__ kdot, int M) {
    extern __shared__ __align__(16) unsigned char dsm[];
    __shared__ float wred[8];
    unsigned sbase = (unsigned)__cvta_generic_to_shared(dsm);
    float* bias_sh = (float*)(dsm + K_SM_BIAS);
    float* aux_sh  = (float*)(dsm + K_SM_AUX);

    int tid = threadIdx.x;
    int lane = tid & 31, wid = tid >> 5;
    int warp_m = wid & 3, warp_n = wid >> 2;
    int rowBase = blockIdx.y * 128;
    int colBase = blockIdx.x * 128;
    const __nv_bfloat16* A = blockIdx.z ? A1 : A0;

    for (int i = tid; i < DK; i += 256) { bias_sh[i] = bias[i]; aux_sh[i] = qsem[i]; }

    float c[2][8][4];
#pragma unroll
    for (int i = 0; i < 2; i++)
#pragma unroll
        for (int j = 0; j < 8; j++)
#pragma unroll
            for (int q = 0; q < 4; q++) c[i][j][q] = 0.f;

    auto issue = [&](int ch) {
        unsigned abase = sbase + (ch % 3) * 32768;
        int k0 = ch * 64;
#pragma unroll
        for (int i = 0; i < 4; i++) {
            int idx = tid + 256 * i;
            {
                int r = idx >> 3, c16 = idx & 7;
                int gr = rowBase + r;
                int sz = (gr < M) ? 16 : 0;
                int ga = gr < M ? gr : (M - 1);
                const __nv_bfloat16* src = A + (size_t)ga * DK + k0 + c16 * 8;
                unsigned dst = abase + (r * 8 + (c16 ^ (r & 7))) * 16;
                asm volatile("cp.async.cg.shared.global [%0], [%1], 16, %2;"
                             :: "r"(dst), "l"(src), "r"(sz));
            }
            {
                int r = idx >> 4, cch = idx & 15;
                const __nv_bfloat16* src = B + (size_t)(k0 + r) * DK + colBase + cch * 8;
                unsigned dst = abase + 16384 + (r * 16 + ((cch & 8) | ((cch & 7) ^ (r & 7)))) * 16;
                asm volatile("cp.async.cg.shared.global [%0], [%1], 16;"
                             :: "r"(dst), "l"(src));
            }
        }
    };

    issue(0); asm volatile("cp.async.commit_group;" ::: "memory");
    issue(1); asm volatile("cp.async.commit_group;" ::: "memory");

    for (int ch = 0; ch < 8; ch++) {
        if (ch == 7) asm volatile("cp.async.wait_group 0;" ::: "memory");
        else         asm volatile("cp.async.wait_group 1;" ::: "memory");
        __syncthreads();
        if (ch + 2 < 8) {
            issue(ch + 2);
            asm volatile("cp.async.commit_group;" ::: "memory");
        }
        unsigned AsB = sbase + (ch % 3) * 32768;
        unsigned BsB = AsB + 16384;
#pragma unroll
        for (int kk = 0; kk < 4; kk++) {
            unsigned a[2][4], b[8][2];
#pragma unroll
            for (int i = 0; i < 2; i++) {
                int m = lane >> 3;
                int r = warp_m * 32 + i * 16 + (m & 1) * 8 + (lane & 7);
                int cch = kk * 2 + (m >> 1);
                unsigned addr = AsB + r * 128 + ((cch ^ (r & 7)) * 16);
                asm volatile("ldmatrix.sync.aligned.m8n8.x4.shared.b16 {%0,%1,%2,%3}, [%4];"
                             : "=r"(a[i][0]), "=r"(a[i][1]), "=r"(a[i][2]), "=r"(a[i][3]) : "r"(addr));
            }
#pragma unroll
            for (int jp = 0; jp < 4; jp++) {
                int m = lane >> 3;
                int kr = kk * 16 + (m & 1) * 8 + (lane & 7);
                int cch = warp_n * 8 + jp * 2 + (m >> 1);
                unsigned addr = BsB + kr * 256 + (((cch & 8) | ((cch & 7) ^ (kr & 7))) * 16);
                asm volatile("ldmatrix.sync.aligned.m8n8.x4.trans.shared.b16 {%0,%1,%2,%3}, [%4];"
                             : "=r"(b[jp*2][0]), "=r"(b[jp*2][1]), "=r"(b[jp*2+1][0]), "=r"(b[jp*2+1][1])
                             : "r"(addr));
            }
#pragma unroll
            for (int i = 0; i < 2; i++)
#pragma unroll
                for (int j = 0; j < 8; j++) {
                    asm volatile(
                        "mma.sync.aligned.m16n8k16.row.col.f32.bf16.bf16.f32 "
                        "{%0,%1,%2,%3}, {%4,%5,%6,%7}, {%8,%9}, {%0,%1,%2,%3};"
                        : "+f"(c[i][j][0]), "+f"(c[i][j][1]), "+f"(c[i][j][2]), "+f"(c[i][j][3])
                        : "r"(a[i][0]), "r"(a[i][1]), "r"(a[i][2]), "r"(a[i][3]),
                          "r"(b[j][0]), "r"(b[j][1]));
                }
        }
    }

    int g = lane >> 2, t = lane & 3;
    float sq = 0.f;
#pragma unroll
    for (int j = 0; j < 8; j++) {
        int col = colBase + warp_n * 64 + j * 8 + 2 * t;
        float b0 = bias_sh[col], b1 = bias_sh[col + 1];
        float q0 = aux_sh[col], q1 = aux_sh[col + 1];
#pragma unroll
        for (int i = 0; i < 2; i++) {
            int r0 = rowBase + warp_m * 32 + i * 16 + g;
            if (r0 < M)
                sq += tanhf(c[i][j][0] + b0) * q0 + tanhf(c[i][j][1] + b1) * q1;
            if (r0 + 8 < M)
                sq += tanhf(c[i][j][2] + b0) * q0 + tanhf(c[i][j][3] + b1) * q1;
        }
    }
#pragma unroll
    for (int off = 16; off > 0; off >>= 1)
        sq += __shfl_xor_sync(0xffffffffu, sq, off);
    if (lane == 0) wred[wid] = sq;
    __syncthreads();
    if (tid == 0) {
        float s = 0.f;
#pragma unroll
        for (int w = 0; w < 8; w++) s += wred[w];
        atomicAdd(&kdot[blockIdx.z], s);
    }
}

// ---------------- padded-CSR build (z selects edge set) ----------------
__global__ void build_csr(const int* __restrict__ dst0, const int* __restrict__ dst1) {
    int e = blockIdx.x * blockDim.x + threadIdx.x;
    if (e >= NE) return;
    const int* dst = blockIdx.z ? dst1 : dst0;
    int* deg = blockIdx.z ? g_deg1 : g_deg0;
    int* slots = blockIdx.z ? g_slots1 : g_slots0;
    int dn = dst[e];
    int pos = atomicAdd(&deg[dn], 1);
    if (pos < CAP) slots[(size_t)dn * CAP + pos] = e;
}

// ---------------- GAT conv (z selects metapath): one warp per dst node,
// 2-pass, smem logits + online softmax, bf16 gather, fused colsum ----------------
__global__ void conv_kernel(const __nv_bfloat16* __restrict__ h0,
                            const __nv_bfloat16* __restrict__ h1,
                            const float* __restrict__ as0, const float* __restrict__ as1,
                            const float* __restrict__ ad0, const float* __restrict__ ad1,
                            const int* __restrict__ es0, const int* __restrict__ es1,
                            float* __restrict__ outsum) {
    __shared__ float al_sm[8][CAP][NH];
    __shared__ int   sidx[8][CAP];
    __shared__ float mx_sm[8][NH];
    __shared__ float den_sm[8][NH];
    __shared__ float bsum[512];
    for (int i = threadIdx.x; i < 512; i += 256) bsum[i] = 0.f;
    __syncthreads();

    int z = blockIdx.z;
    const __nv_bfloat16* hsrc = z ? h1 : h0;
    const float* asrc = z ? as1 : as0;
    const float* adst = z ? ad1 : ad0;
    const int* esrc = z ? es1 : es0;
    const int* deg = z ? g_deg1 : g_deg0;
    const int* slots = z ? g_slots1 : g_slots0;
    __nv_bfloat16* outp = z ? g_out1 : g_out0;

    int warp = threadIdx.x >> 5, lane = threadIdx.x & 31;
    int n = blockIdx.x * 8 + warp;
    float acc[16];
#pragma unroll
    for (int r = 0; r < 16; r++) acc[r] = 0.f;

    if (n < N_NODE) {
        int d = deg[n]; if (d > CAP) d = CAP;
        if (d > 0) {
            int h = lane & 7, q = lane >> 3;
            float ad = adst[(size_t)n * NH + h];
            const int* sl = slots + (size_t)n * CAP;

            float mx = -1e30f, den = 0.f;
            for (int j0 = 0; j0 < d; j0 += 4) {
                int jj = j0 + q;
                if (jj < d) {
                    int s = esrc[sl[jj]];
                    if (h == 0) sidx[warp][jj] = s;
                    float al = asrc[(size_t)s * NH + h] + ad;
                    al = al > 0.f ? al : 0.2f * al;
                    al_sm[warp][jj][h] = al;
                    float nm = fmaxf(mx, al);
                    den = den * __expf(mx - nm) + __expf(al - nm);
                    mx = nm;
                }
            }
#pragma unroll
            for (int off = 8; off <= 16; off <<= 1) {
                float mo = __shfl_xor_sync(0xffffffffu, mx, off);
                float dn_ = __shfl_xor_sync(0xffffffffu, den, off);
                float nm = fmaxf(mx, mo);
                den = den * __expf(mx - nm) + dn_ * __expf(mo - nm);
                mx = nm;
            }
            if (q == 0) { mx_sm[warp][h] = mx; den_sm[warp][h] = den + 1e-16f; }
            __syncwarp();

            int h1s = lane >> 3, h2s = 4 + h1s;
            float m1 = mx_sm[warp][h1s], d1 = den_sm[warp][h1s];
            float m2 = mx_sm[warp][h2s], d2 = den_sm[warp][h2s];
            for (int j = 0; j < d; j++) {
                int s = sidx[warp][j];
                float w1 = __expf(al_sm[warp][j][h1s] - m1) / d1;
                float w2 = __expf(al_sm[warp][j][h2s] - m2) / d2;
                const uint4* hp = reinterpret_cast<const uint4*>(hsrc + (size_t)s * DK);
                uint4 v1 = hp[lane];
                uint4 v2 = hp[lane + 32];
                const unsigned* u1 = &v1.x;
                const unsigned* u2 = &v2.x;
#pragma unroll
                for (int qq = 0; qq < 4; qq++) {
                    float2 f1 = unpack_bf16(u1[qq]);
                    float2 f2 = unpack_bf16(u2[qq]);
                    acc[qq * 2 + 0] += f1.x * w1; acc[qq * 2 + 1] += f1.y * w1;
                    acc[8 + qq * 2 + 0] += f2.x * w2; acc[8 + qq * 2 + 1] += f2.y * w2;
                }
            }
        }
        uint4 o1, o2;
        unsigned* p1 = &o1.x; unsigned* p2 = &o2.x;
#pragma unroll
        for (int qq = 0; qq < 4; qq++) {
            float a0 = fmaxf(acc[qq*2+0], 0.f),  a1 = fmaxf(acc[qq*2+1], 0.f);
            float b0 = fmaxf(acc[8+qq*2+0], 0.f), b1 = fmaxf(acc[8+qq*2+1], 0.f);
            p1[qq] = pack_bf16(a0, a1);
            p2[qq] = pack_bf16(b0, b1);
            atomicAdd(&bsum[lane * 8 + qq * 2 + 0], a0);
            atomicAdd(&bsum[lane * 8 + qq * 2 + 1], a1);
            atomicAdd(&bsum[256 + lane * 8 + qq * 2 + 0], b0);
            atomicAdd(&bsum[256 + lane * 8 + qq * 2 + 1], b1);
        }
        uint4* op = reinterpret_cast<uint4*>(outp + (size_t)n * DK);
        op[lane] = o1; op[lane + 32] = o2;
    }
    __syncthreads();
    float* osum = outsum + (size_t)z * DK;
    for (int i = threadIdx.x; i < 512; i += 256) atomicAdd(&osum[i], bsum[i]);
}

// ---------------- finalize ----------------
__global__ void finalize_kernel(const float* __restrict__ lw,
                                const float* __restrict__ lb,
                                float* __restrict__ out) {
    __shared__ float red0[512], red1[512];
    __shared__ float sem0s, sem1s;
    int t = threadIdx.x;
    if (t == 0) {
        float s0 = g_kdot[0] / (float)N_NODE;
        float s1 = g_kdot[1] / (float)N_NODE;
        float mx = fmaxf(s0, s1);
        float e0 = expf(s0 - mx), e1 = expf(s1 - mx);
        sem0s = e0 / (e0 + e1);
        sem1s = e1 / (e0 + e1);
    }
    __syncthreads();
    float pooled = (sem0s * g_outsum[t] + sem1s * g_outsum[DK + t]) / (float)N_NODE;
    red0[t] = pooled * lw[t * 2 + 0];
    red1[t] = pooled * lw[t * 2 + 1];
    __syncthreads();
    for (int s = 256; s > 0; s >>= 1) {
        if (t < s) { red0[t] += red0[t + s]; red1[t] += red1[t + s]; }
        __syncthreads();
    }
    if (t == 0) {
        out[0] = red0[0] + lb[0];
        out[1] = red1[0] + lb[1];
    }
}

// ---------------- launch ----------------
extern "C" void kernel_launch(void* const* d_in, const int* in_sizes, int n_in,
                              void* d_out, int out_size) {
    const float* x_o        = (const float*)d_in[0];
    const float* x_e        = (const float*)d_in[1];
    const int*   e_e2o      = (const int*)d_in[2];
    const int*   e_o2o      = (const int*)d_in[3];
    const float* proj_o_w   = (const float*)d_in[4];
    const float* proj_o_b   = (const float*)d_in[5];
    const float* proj_e_w   = (const float*)d_in[6];
    const float* proj_e_b   = (const float*)d_in[7];
    const float* att_src_e2o= (const float*)d_in[8];
    const float* att_dst_e2o= (const float*)d_in[9];
    const float* att_src_o2o= (const float*)d_in[10];
    const float* att_dst_o2o= (const float*)d_in[11];
    const float* k_lin_w    = (const float*)d_in[12];
    const float* k_lin_b    = (const float*)d_in[13];
    const float* q_sem      = (const float*)d_in[14];
    const float* lin_w      = (const float*)d_in[15];
    const float* lin_b      = (const float*)d_in[16];
    float* out = (float*)d_out;

    __nv_bfloat16 *h_o, *h_e, *out0, *out1, *bw_o, *bw_e, *bw_k;
    float *a_e_src, *a_o_dst_e2o, *a_o_src_o2o, *a_o_dst_o2o, *kdot, *outsum;
    cudaGetSymbolAddress((void**)&h_o, g_h_o);
    cudaGetSymbolAddress((void**)&h_e, g_h_e);
    cudaGetSymbolAddress((void**)&out0, g_out0);
    cudaGetSymbolAddress((void**)&out1, g_out1);
    cudaGetSymbolAddress((void**)&bw_o, g_bw_o);
    cudaGetSymbolAddress((void**)&bw_e, g_bw_e);
    cudaGetSymbolAddress((void**)&bw_k, g_bw_k);
    cudaGetSymbolAddress((void**)&a_e_src, g_a_e_src);
    cudaGetSymbolAddress((void**)&a_o_dst_e2o, g_a_o_dst_e2o);
    cudaGetSymbolAddress((void**)&a_o_src_o2o, g_a_o_src_o2o);
    cudaGetSymbolAddress((void**)&a_o_dst_o2o, g_a_o_dst_o2o);
    cudaGetSymbolAddress((void**)&kdot, g_kdot);
    cudaGetSymbolAddress((void**)&outsum, g_outsum);

    cudaFuncSetAttribute(proj_gemm<3>, cudaFuncAttributeMaxDynamicSharedMemorySize, P_SM_TOTAL);
    cudaFuncSetAttribute(proj_gemm<1>, cudaFuncAttributeMaxDynamicSharedMemorySize, P_SM_TOTAL);
    cudaFuncSetAttribute(ksum_gemm, cudaFuncAttributeMaxDynamicSharedMemorySize, K_SM_TOTAL);

    dim3 projGrid(DK / 128, (N_NODE + 127) / 128, 1);
    dim3 kGrid(DK / 128, (N_NODE + 127) / 128, 2);
    dim3 csrGrid((NE + 255) / 256, 1, 2);
    dim3 convGrid((N_NODE + 7) / 8, 1, 2);
    int prepThreads = 3 * DK * DK / 2;

    prep_kernel<<<(prepThreads + 255) / 256, 256>>>(proj_o_w, proj_e_w, k_lin_w);

    proj_gemm<3><<<projGrid, 256, P_SM_TOTAL>>>(
        x_o, bw_o, proj_o_b, h_o,
        att_dst_e2o, att_src_o2o, att_dst_o2o,
        a_o_dst_e2o, a_o_src_o2o, a_o_dst_o2o, N_NODE);
    proj_gemm<1><<<projGrid, 256, P_SM_TOTAL>>>(
        x_e, bw_e, proj_e_b, h_e,
        att_src_e2o, nullptr, nullptr,
        a_e_src, nullptr, nullptr, N_NODE);

    build_csr<<<csrGrid, 256>>>(e_e2o + NE, e_o2o + NE);

    conv_kernel<<<convGrid, 256>>>(h_e, h_o,
                                   a_e_src, a_o_src_o2o,
                                   a_o_dst_e2o, a_o_dst_o2o,
                                   e_e2o, e_o2o, outsum);

    ksum_gemm<<<kGrid, 256, K_SM_TOTAL>>>(out0, out1, bw_k, k_lin_b,
                                          q_sem, kdot, N_NODE);

    finalize_kernel<<<1, 512>>>(lin_w, lin_b, out);
}

// round 14
// speedup vs baseline: 1.1628x; 1.1628x over previous
#include <cuda_runtime.h>
#include <cuda_bf16.h>
#include <math.h>

#define N_NODE 100000
#define NE     150000
#define DK     512
#define NH     8
#define CAP    64

// ---------------- scratch (device globals, allocation-free) ----------------
__device__ __nv_bfloat16 g_h_o[(size_t)N_NODE * DK];
__device__ __nv_bfloat16 g_h_e[(size_t)N_NODE * DK];
__device__ __nv_bfloat16 g_out0[(size_t)N_NODE * DK];
__device__ __nv_bfloat16 g_out1[(size_t)N_NODE * DK];
__device__ __nv_bfloat16 g_x_o_bf[(size_t)N_NODE * DK];
__device__ __nv_bfloat16 g_x_e_bf[(size_t)N_NODE * DK];

__device__ __nv_bfloat16 g_bw_o[DK * DK];   // bf16 weights, [k, n] layout
__device__ __nv_bfloat16 g_bw_e[DK * DK];
__device__ __nv_bfloat16 g_bw_k[DK * DK];

__device__ float g_a_e_src[(size_t)N_NODE * NH];
__device__ float g_a_o_dst_e2o[(size_t)N_NODE * NH];
__device__ float g_a_o_src_o2o[(size_t)N_NODE * NH];
__device__ float g_a_o_dst_o2o[(size_t)N_NODE * NH];

__device__ int g_deg0[N_NODE];
__device__ int g_deg1[N_NODE];
__device__ int g_slots0[(size_t)N_NODE * CAP];
__device__ int g_slots1[(size_t)N_NODE * CAP];

__device__ float g_kdot[2];
__device__ float g_outsum[2 * DK];

__device__ __forceinline__ unsigned pack_bf16(float x, float y) {
    __nv_bfloat162 h = __floats2bfloat162_rn(x, y);
    return *reinterpret_cast<unsigned*>(&h);
}
__device__ __forceinline__ float2 unpack_bf16(unsigned u) {
    __nv_bfloat162 h = *reinterpret_cast<__nv_bfloat162*>(&u);
    return __bfloat1622float2(h);
}

// ---------------- prep: init counters + all 3 weight converts, one launch ----------------
__global__ void prep_kernel(const float* __restrict__ w0, const float* __restrict__ w1,
                            const float* __restrict__ w2) {
    int i = blockIdx.x * blockDim.x + threadIdx.x;
    const int WP = DK * DK / 2;
    if (i < 3 * WP) {
        const float* W = (i < WP) ? w0 : (i < 2 * WP) ? w1 : w2;
        __nv_bfloat16* O = (i < WP) ? g_bw_o : (i < 2 * WP) ? g_bw_e : g_bw_k;
        int j = (i < WP) ? i : (i < 2 * WP) ? i - WP : i - 2 * WP;
        float2 f = reinterpret_cast<const float2*>(W)[j];
        reinterpret_cast<unsigned*>(O)[j] = pack_bf16(f.x, f.y);
    }
    if (i < N_NODE) { g_deg0[i] = 0; g_deg1[i] = 0; }
    if (i < 2 * DK) g_outsum[i] = 0.f;
    if (i < 2) g_kdot[i] = 0.f;
}

// ---------------- x fp32 -> bf16 (z selects array), float4 granularity ----------------
__global__ void convert_x(const float* __restrict__ x0, const float* __restrict__ x1,
                          int n4) {
    int i = blockIdx.x * blockDim.x + threadIdx.x;
    if (i < n4) {
        const float* X = blockIdx.z ? x1 : x0;
        __nv_bfloat16* O = blockIdx.z ? g_x_e_bf : g_x_o_bf;
        float4 f = reinterpret_cast<const float4*>(X)[i];
        uint2 o;
        o.x = pack_bf16(f.x, f.y);
        o.y = pack_bf16(f.z, f.w);
        reinterpret_cast<uint2*>(O)[i] = o;
    }
}

// =====================================================================
// bf16 mma.sync GEMM with 3-stage cp.async pipeline (R8-proven core).
// C[M,512] = A[M,512] @ B[512,512]  (A, B both bf16)
// EPI 0: bias + store bf16 C + NATT fused per-head attention dots
// EPI 1: sum_n sum_f tanh(c+bias)*q[f] -> one atomicAdd(kdot[z]) per block
// __launch_bounds__(256, 2): cap regs at 128 so 2 CTAs/SM co-reside
// (2 x 106KB smem = 212KB <= 228KB).
// =====================================================================
#define SM_BIAS   98304
#define SM_AUX    (98304 + 2048)
#define SM_TOTAL  (98304 + 2048 + 6144)

template<int EPI, int NATT>
__global__ __launch_bounds__(256, 2)
void mma_gemm(const __nv_bfloat16* __restrict__ A0, const __nv_bfloat16* __restrict__ A1,
              const __nv_bfloat16* __restrict__ B,
              const float* __restrict__ bias, __nv_bfloat16* __restrict__ Cout,
              const float* __restrict__ av0, const float* __restrict__ av1,
              const float* __restrict__ av2,
              float* __restrict__ aout0, float* __restrict__ aout1,
              float* __restrict__ aout2,
              const float* __restrict__ qsem, float* __restrict__ kdot, int M) {
    extern __shared__ __align__(16) unsigned char dsm[];
    __shared__ float wred[8];
    unsigned sbase = (unsigned)__cvta_generic_to_shared(dsm);
    float* bias_sh = (float*)(dsm + SM_BIAS);
    float* aux_sh  = (float*)(dsm + SM_AUX);

    int tid = threadIdx.x;
    int lane = tid & 31, wid = tid >> 5;
    int warp_m = wid & 3, warp_n = wid >> 2;      // 4 x 2 warps; warp tile 32x64
    int rowBase = blockIdx.y * 128;
    int colBase = blockIdx.x * 128;

    const __nv_bfloat16* A = (EPI == 1 && blockIdx.z == 1) ? A1 : A0;

    for (int i = tid; i < DK; i += 256) {
        bias_sh[i] = bias[i];
        if (EPI == 1) aux_sh[i] = qsem[i];
    }
    if (EPI == 0 && NATT > 0) {
        for (int i = tid; i < NATT * DK; i += 256) {
            const float* src = (i < DK) ? av0 : (i < 2 * DK) ? av1 : av2;
            aux_sh[i] = src[i & (DK - 1)];
        }
    }

    float c[2][8][4];
#pragma unroll
    for (int i = 0; i < 2; i++)
#pragma unroll
        for (int j = 0; j < 8; j++)
#pragma unroll
            for (int q = 0; q < 4; q++) c[i][j][q] = 0.f;

    auto issue = [&](int ch) {
        unsigned abase = sbase + (ch % 3) * 32768;
        int k0 = ch * 64;
#pragma unroll
        for (int i = 0; i < 4; i++) {
            int idx = tid + 256 * i;
            {   // A tile: 128 rows x 128B
                int r = idx >> 3, c16 = idx & 7;
                int gr = rowBase + r;
                int sz = (gr < M) ? 16 : 0;
                int ga = gr < M ? gr : (M - 1);
                const __nv_bfloat16* src = A + (size_t)ga * DK + k0 + c16 * 8;
                unsigned dst = abase + (r * 8 + (c16 ^ (r & 7))) * 16;
                asm volatile("cp.async.cg.shared.global [%0], [%1], 16, %2;"
                             :: "r"(dst), "l"(src), "r"(sz));
            }
            {   // B tile: 64 rows x 256B
                int r = idx >> 4, cch = idx & 15;
                const __nv_bfloat16* src = B + (size_t)(k0 + r) * DK + colBase + cch * 8;
                unsigned dst = abase + 16384 + (r * 16 + ((cch & 8) | ((cch & 7) ^ (r & 7)))) * 16;
                asm volatile("cp.async.cg.shared.global [%0], [%1], 16;"
                             :: "r"(dst), "l"(src));
            }
        }
    };

    issue(0); asm volatile("cp.async.commit_group;" ::: "memory");
    issue(1); asm volatile("cp.async.commit_group;" ::: "memory");

    for (int ch = 0; ch < 8; ch++) {
        if (ch == 7) asm volatile("cp.async.wait_group 0;" ::: "memory");
        else         asm volatile("cp.async.wait_group 1;" ::: "memory");
        __syncthreads();
        if (ch + 2 < 8) {
            issue(ch + 2);
            asm volatile("cp.async.commit_group;" ::: "memory");
        }
        unsigned AsB = sbase + (ch % 3) * 32768;
        unsigned BsB = AsB + 16384;
#pragma unroll
        for (int kk = 0; kk < 4; kk++) {
            unsigned a[2][4], b[8][2];
#pragma unroll
            for (int i = 0; i < 2; i++) {
                int m = lane >> 3;
                int r = warp_m * 32 + i * 16 + (m & 1) * 8 + (lane & 7);
                int cch = kk * 2 + (m >> 1);
                unsigned addr = AsB + r * 128 + ((cch ^ (r & 7)) * 16);
                asm volatile("ldmatrix.sync.aligned.m8n8.x4.shared.b16 {%0,%1,%2,%3}, [%4];"
                             : "=r"(a[i][0]), "=r"(a[i][1]), "=r"(a[i][2]), "=r"(a[i][3]) : "r"(addr));
            }
#pragma unroll
            for (int jp = 0; jp < 4; jp++) {
                int m = lane >> 3;
                int kr = kk * 16 + (m & 1) * 8 + (lane & 7);
                int cch = warp_n * 8 + jp * 2 + (m >> 1);
                unsigned addr = BsB + kr * 256 + (((cch & 8) | ((cch & 7) ^ (kr & 7))) * 16);
                asm volatile("ldmatrix.sync.aligned.m8n8.x4.trans.shared.b16 {%0,%1,%2,%3}, [%4];"
                             : "=r"(b[jp*2][0]), "=r"(b[jp*2][1]), "=r"(b[jp*2+1][0]), "=r"(b[jp*2+1][1])
                             : "r"(addr));
            }
#pragma unroll
            for (int i = 0; i < 2; i++)
#pragma unroll
                for (int j = 0; j < 8; j++) {
                    asm volatile(
                        "mma.sync.aligned.m16n8k16.row.col.f32.bf16.bf16.f32 "
                        "{%0,%1,%2,%3}, {%4,%5,%6,%7}, {%8,%9}, {%0,%1,%2,%3};"
                        : "+f"(c[i][j][0]), "+f"(c[i][j][1]), "+f"(c[i][j][2]), "+f"(c[i][j][3])
                        : "r"(a[i][0]), "r"(a[i][1]), "r"(a[i][2]), "r"(a[i][3]),
                          "r"(b[j][0]), "r"(b[j][1]));
                }
        }
    }

    // ---------------- epilogue ----------------
    int g = lane >> 2, t = lane & 3;
    if (EPI == 0) {
        __nv_bfloat16* C = Cout;
        float aacc[(NATT > 0 ? NATT : 1)][4];
#pragma unroll
        for (int v = 0; v < (NATT > 0 ? NATT : 1); v++)
#pragma unroll
            for (int f = 0; f < 4; f++) aacc[v][f] = 0.f;

#pragma unroll
        for (int j = 0; j < 8; j++) {
            int col = colBase + warp_n * 64 + j * 8 + 2 * t;
            float b0 = bias_sh[col], b1 = bias_sh[col + 1];
#pragma unroll
            for (int i = 0; i < 2; i++) {
                int r0 = rowBase + warp_m * 32 + i * 16 + g;
                float v0 = c[i][j][0] + b0, v1 = c[i][j][1] + b1;
                float v2 = c[i][j][2] + b0, v3 = c[i][j][3] + b1;
                if (r0 < M)
                    *reinterpret_cast<unsigned*>(C + (size_t)r0 * DK + col) = pack_bf16(v0, v1);
                if (r0 + 8 < M)
                    *reinterpret_cast<unsigned*>(C + (size_t)(r0 + 8) * DK + col) = pack_bf16(v2, v3);
#pragma unroll
                for (int v = 0; v < NATT; v++) {
                    float a0 = aux_sh[v * DK + col], a1 = aux_sh[v * DK + col + 1];
                    aacc[v][i * 2 + 0] += v0 * a0 + v1 * a1;
                    aacc[v][i * 2 + 1] += v2 * a0 + v3 * a1;
                }
            }
        }
        if (NATT > 0) {
            // reduce over the 4 't' lanes (each (bx, warp_n) owns one head's 64 cols)
#pragma unroll
            for (int v = 0; v < NATT; v++)
#pragma unroll
                for (int f = 0; f < 4; f++) {
                    aacc[v][f] += __shfl_xor_sync(0xffffffffu, aacc[v][f], 1);
                    aacc[v][f] += __shfl_xor_sync(0xffffffffu, aacc[v][f], 2);
                }
            if (t == 0) {
                int ghead = blockIdx.x * 2 + warp_n;
#pragma unroll
                for (int f = 0; f < 4; f++) {
                    int row = rowBase + warp_m * 32 + (f & 1) * 8 + (f >> 1) * 16 + g;
                    if (row < M) {
#pragma unroll
                        for (int v = 0; v < NATT; v++) {
                            float* ao = (v == 0) ? aout0 : (v == 1) ? aout1 : aout2;
                            ao[(size_t)row * NH + ghead] = aacc[v][f];
                        }
                    }
                }
            }
        }
    } else {
        float sq = 0.f;
#pragma unroll
        for (int j = 0; j < 8; j++) {
            int col = colBase + warp_n * 64 + j * 8 + 2 * t;
            float b0 = bias_sh[col], b1 = bias_sh[col + 1];
            float q0 = aux_sh[col], q1 = aux_sh[col + 1];
#pragma unroll
            for (int i = 0; i < 2; i++) {
                int r0 = rowBase + warp_m * 32 + i * 16 + g;
                if (r0 < M)
                    sq += tanhf(c[i][j][0] + b0) * q0 + tanhf(c[i][j][1] + b1) * q1;
                if (r0 + 8 < M)
                    sq += tanhf(c[i][j][2] + b0) * q0 + tanhf(c[i][j][3] + b1) * q1;
            }
        }
#pragma unroll
        for (int off = 16; off > 0; off >>= 1)
            sq += __shfl_xor_sync(0xffffffffu, sq, off);
        if (lane == 0) wred[wid] = sq;
        __syncthreads();
        if (tid == 0) {
            float s = 0.f;
#pragma unroll
            for (int w = 0; w < 8; w++) s += wred[w];
            atomicAdd(&kdot[blockIdx.z], s);
        }
    }
}

// ---------------- padded-CSR build (z selects edge set) ----------------
__global__ void build_csr(const int* __restrict__ dst0, const int* __restrict__ dst1) {
    int e = blockIdx.x * blockDim.x + threadIdx.x;
    if (e >= NE) return;
    const int* dst = blockIdx.z ? dst1 : dst0;
    int* deg = blockIdx.z ? g_deg1 : g_deg0;
    int* slots = blockIdx.z ? g_slots1 : g_slots0;
    int dn = dst[e];
    int pos = atomicAdd(&deg[dn], 1);
    if (pos < CAP) slots[(size_t)dn * CAP + pos] = e;
}

// ---------------- GAT conv (z selects metapath): one warp per dst node,
// 2-pass, smem logits + online softmax, bf16 gather, fused colsum ----------------
__global__ void conv_kernel(const __nv_bfloat16* __restrict__ h0,
                            const __nv_bfloat16* __restrict__ h1,
                            const float* __restrict__ as0, const float* __restrict__ as1,
                            const float* __restrict__ ad0, const float* __restrict__ ad1,
                            const int* __restrict__ es0, const int* __restrict__ es1,
                            float* __restrict__ outsum) {
    __shared__ float al_sm[8][CAP][NH];
    __shared__ int   sidx[8][CAP];
    __shared__ float mx_sm[8][NH];
    __shared__ float den_sm[8][NH];
    __shared__ float bsum[512];
    for (int i = threadIdx.x; i < 512; i += 256) bsum[i] = 0.f;
    __syncthreads();

    int z = blockIdx.z;
    const __nv_bfloat16* hsrc = z ? h1 : h0;
    const float* asrc = z ? as1 : as0;
    const float* adst = z ? ad1 : ad0;
    const int* esrc = z ? es1 : es0;
    const int* deg = z ? g_deg1 : g_deg0;
    const int* slots = z ? g_slots1 : g_slots0;
    __nv_bfloat16* outp = z ? g_out1 : g_out0;

    int warp = threadIdx.x >> 5, lane = threadIdx.x & 31;
    int n = blockIdx.x * 8 + warp;
    float acc[16];
#pragma unroll
    for (int r = 0; r < 16; r++) acc[r] = 0.f;

    if (n < N_NODE) {
        int d = deg[n]; if (d > CAP) d = CAP;
        if (d > 0) {
            int h = lane & 7, q = lane >> 3;
            float ad = adst[(size_t)n * NH + h];
            const int* sl = slots + (size_t)n * CAP;

            float mx = -1e30f, den = 0.f;
            for (int j0 = 0; j0 < d; j0 += 4) {
                int jj = j0 + q;
                if (jj < d) {
                    int s = esrc[sl[jj]];
                    if (h == 0) sidx[warp][jj] = s;
                    float al = asrc[(size_t)s * NH + h] + ad;
                    al = al > 0.f ? al : 0.2f * al;
                    al_sm[warp][jj][h] = al;
                    float nm = fmaxf(mx, al);
                    den = den * __expf(mx - nm) + __expf(al - nm);
                    mx = nm;
                }
            }
#pragma unroll
            for (int off = 8; off <= 16; off <<= 1) {
                float mo = __shfl_xor_sync(0xffffffffu, mx, off);
                float dn_ = __shfl_xor_sync(0xffffffffu, den, off);
                float nm = fmaxf(mx, mo);
                den = den * __expf(mx - nm) + dn_ * __expf(mo - nm);
                mx = nm;
            }
            if (q == 0) { mx_sm[warp][h] = mx; den_sm[warp][h] = den + 1e-16f; }
            __syncwarp();

            int h1s = lane >> 3, h2s = 4 + h1s;
            float m1 = mx_sm[warp][h1s], d1 = den_sm[warp][h1s];
            float m2 = mx_sm[warp][h2s], d2 = den_sm[warp][h2s];
            for (int j = 0; j < d; j++) {
                int s = sidx[warp][j];
                float w1 = __expf(al_sm[warp][j][h1s] - m1) / d1;
                float w2 = __expf(al_sm[warp][j][h2s] - m2) / d2;
                const uint4* hp = reinterpret_cast<const uint4*>(hsrc + (size_t)s * DK);
                uint4 v1 = hp[lane];
                uint4 v2 = hp[lane + 32];
                const unsigned* u1 = &v1.x;
                const unsigned* u2 = &v2.x;
#pragma unroll
                for (int qq = 0; qq < 4; qq++) {
                    float2 f1 = unpack_bf16(u1[qq]);
                    float2 f2 = unpack_bf16(u2[qq]);
                    acc[qq * 2 + 0] += f1.x * w1; acc[qq * 2 + 1] += f1.y * w1;
                    acc[8 + qq * 2 + 0] += f2.x * w2; acc[8 + qq * 2 + 1] += f2.y * w2;
                }
            }
        }
        uint4 o1, o2;
        unsigned* p1 = &o1.x; unsigned* p2 = &o2.x;
#pragma unroll
        for (int qq = 0; qq < 4; qq++) {
            float a0 = fmaxf(acc[qq*2+0], 0.f),  a1 = fmaxf(acc[qq*2+1], 0.f);
            float b0 = fmaxf(acc[8+qq*2+0], 0.f), b1 = fmaxf(acc[8+qq*2+1], 0.f);
            p1[qq] = pack_bf16(a0, a1);
            p2[qq] = pack_bf16(b0, b1);
            atomicAdd(&bsum[lane * 8 + qq * 2 + 0], a0);
            atomicAdd(&bsum[lane * 8 + qq * 2 + 1], a1);
            atomicAdd(&bsum[256 + lane * 8 + qq * 2 + 0], b0);
            atomicAdd(&bsum[256 + lane * 8 + qq * 2 + 1], b1);
        }
        uint4* op = reinterpret_cast<uint4*>(outp + (size_t)n * DK);
        op[lane] = o1; op[lane + 32] = o2;
    }
    __syncthreads();
    float* osum = outsum + (size_t)z * DK;
    for (int i = threadIdx.x; i < 512; i += 256) atomicAdd(&osum[i], bsum[i]);
}

// ---------------- finalize ----------------
__global__ void finalize_kernel(const float* __restrict__ lw,
                                const float* __restrict__ lb,
                                float* __restrict__ out) {
    __shared__ float red0[512], red1[512];
    __shared__ float sem0s, sem1s;
    int t = threadIdx.x;
    if (t == 0) {
        float s0 = g_kdot[0] / (float)N_NODE;
        float s1 = g_kdot[1] / (float)N_NODE;
        float mx = fmaxf(s0, s1);
        float e0 = expf(s0 - mx), e1 = expf(s1 - mx);
        sem0s = e0 / (e0 + e1);
        sem1s = e1 / (e0 + e1);
    }
    __syncthreads();
    float pooled = (sem0s * g_outsum[t] + sem1s * g_outsum[DK + t]) / (float)N_NODE;
    red0[t] = pooled * lw[t * 2 + 0];
    red1[t] = pooled * lw[t * 2 + 1];
    __syncthreads();
    for (int s = 256; s > 0; s >>= 1) {
        if (t < s) { red0[t] += red0[t + s]; red1[t] += red1[t + s]; }
        __syncthreads();
    }
    if (t == 0) {
        out[0] = red0[0] + lb[0];
        out[1] = red1[0] + lb[1];
    }
}

// ---------------- launch ----------------
extern "C" void kernel_launch(void* const* d_in, const int* in_sizes, int n_in,
                              void* d_out, int out_size) {
    const float* x_o        = (const float*)d_in[0];
    const float* x_e        = (const float*)d_in[1];
    const int*   e_e2o      = (const int*)d_in[2];
    const int*   e_o2o      = (const int*)d_in[3];
    const float* proj_o_w   = (const float*)d_in[4];
    const float* proj_o_b   = (const float*)d_in[5];
    const float* proj_e_w   = (const float*)d_in[6];
    const float* proj_e_b   = (const float*)d_in[7];
    const float* att_src_e2o= (const float*)d_in[8];
    const float* att_dst_e2o= (const float*)d_in[9];
    const float* att_src_o2o= (const float*)d_in[10];
    const float* att_dst_o2o= (const float*)d_in[11];
    const float* k_lin_w    = (const float*)d_in[12];
    const float* k_lin_b    = (const float*)d_in[13];
    const float* q_sem      = (const float*)d_in[14];
    const float* lin_w      = (const float*)d_in[15];
    const float* lin_b      = (const float*)d_in[16];
    float* out = (float*)d_out;

    __nv_bfloat16 *h_o, *h_e, *out0, *out1, *bw_o, *bw_e, *bw_k, *x_o_bf, *x_e_bf;
    float *a_e_src, *a_o_dst_e2o, *a_o_src_o2o, *a_o_dst_o2o, *kdot, *outsum;
    cudaGetSymbolAddress((void**)&h_o, g_h_o);
    cudaGetSymbolAddress((void**)&h_e, g_h_e);
    cudaGetSymbolAddress((void**)&out0, g_out0);
    cudaGetSymbolAddress((void**)&out1, g_out1);
    cudaGetSymbolAddress((void**)&bw_o, g_bw_o);
    cudaGetSymbolAddress((void**)&bw_e, g_bw_e);
    cudaGetSymbolAddress((void**)&bw_k, g_bw_k);
    cudaGetSymbolAddress((void**)&x_o_bf, g_x_o_bf);
    cudaGetSymbolAddress((void**)&x_e_bf, g_x_e_bf);
    cudaGetSymbolAddress((void**)&a_e_src, g_a_e_src);
    cudaGetSymbolAddress((void**)&a_o_dst_e2o, g_a_o_dst_e2o);
    cudaGetSymbolAddress((void**)&a_o_src_o2o, g_a_o_src_o2o);
    cudaGetSymbolAddress((void**)&a_o_dst_o2o, g_a_o_dst_o2o);
    cudaGetSymbolAddress((void**)&kdot, g_kdot);
    cudaGetSymbolAddress((void**)&outsum, g_outsum);

    cudaFuncSetAttribute(mma_gemm<0,3>, cudaFuncAttributeMaxDynamicSharedMemorySize, SM_TOTAL);
    cudaFuncSetAttribute(mma_gemm<0,1>, cudaFuncAttributeMaxDynamicSharedMemorySize, SM_TOTAL);
    cudaFuncSetAttribute(mma_gemm<1,0>, cudaFuncAttributeMaxDynamicSharedMemorySize, SM_TOTAL);

    dim3 projGrid(DK / 128, (N_NODE + 127) / 128, 1);
    dim3 kGrid(DK / 128, (N_NODE + 127) / 128, 2);
    dim3 csrGrid((NE + 255) / 256, 1, 2);
    dim3 convGrid((N_NODE + 7) / 8, 1, 2);
    int xN4 = N_NODE * DK / 4;
    dim3 xGrid((xN4 + 255) / 256, 1, 2);
    int prepThreads = 3 * DK * DK / 2;

    prep_kernel<<<(prepThreads + 255) / 256, 256>>>(proj_o_w, proj_e_w, k_lin_w);
    convert_x<<<xGrid, 256>>>(x_o, x_e, xN4);

    mma_gemm<0,3><<<projGrid, 256, SM_TOTAL>>>(
        x_o_bf, nullptr, bw_o, proj_o_b, h_o,
        att_dst_e2o, att_src_o2o, att_dst_o2o,
        a_o_dst_e2o, a_o_src_o2o, a_o_dst_o2o,
        nullptr, nullptr, N_NODE);
    mma_gemm<0,1><<<projGrid, 256, SM_TOTAL>>>(
        x_e_bf, nullptr, bw_e, proj_e_b, h_e,
        att_src_e2o, nullptr, nullptr,
        a_e_src, nullptr, nullptr,
        nullptr, nullptr, N_NODE);

    build_csr<<<csrGrid, 256>>>(e_e2o + NE, e_o2o + NE);

    conv_kernel<<<convGrid, 256>>>(h_e, h_o,
                                   a_e_src, a_o_src_o2o,
                                   a_o_dst_e2o, a_o_dst_o2o,
                                   e_e2o, e_o2o, outsum);

    mma_gemm<1,0><<<kGrid, 256, SM_TOTAL>>>(
        out0, out1, bw_k, k_lin_b, nullptr,
        nullptr, nullptr, nullptr, nullptr, nullptr, nullptr,
        q_sem, kdot, N_NODE);

    finalize_kernel<<<1, 512>>>(lin_w, lin_b, out);
}